// round 1
// baseline (speedup 1.0000x reference)
#include <cuda_runtime.h>
#include <cuda_bf16.h>

#define B_DIM 8
#define N_PTS 2048
#define NPTS_TOTAL (B_DIM * N_PTS)
#define C_OUT 128
#define H_DIM 64
#define NSAMPLE 64
#define R2 0.36f

// Scratch (allocation-free rule: __device__ globals)
__device__ float  g_f[NPTS_TOTAL * C_OUT];   // per-point 128-dim features (8 MB)
__device__ float4 g_xpad[NPTS_TOTAL];        // (x, y, z, x^2+y^2+z^2)

// ---------------------------------------------------------------------------
// Kernel 1: per-point MLP features.  One warp per point.
//   h1[o] = relu(W1[o,:] . x + b1[o])        o in [0,64)
//   f[c]  = relu(W2[c,:] . h1 + b2[c])       c in [0,128)
// W2 staged transposed in smem for conflict-free lane access.
// ---------------------------------------------------------------------------
__global__ void feat_kernel(const float* __restrict__ x,
                            const float* __restrict__ W1,
                            const float* __restrict__ b1,
                            const float* __restrict__ W2,
                            const float* __restrict__ b2)
{
    __shared__ float sW1[H_DIM * 3];
    __shared__ float sb1[H_DIM];
    __shared__ float sW2t[H_DIM * C_OUT];   // [k][o]
    __shared__ float sb2[C_OUT];
    __shared__ float sh1[8][H_DIM];         // per-warp h1

    const int tid = threadIdx.x;
    for (int i = tid; i < H_DIM * 3; i += blockDim.x) sW1[i] = W1[i];
    for (int i = tid; i < H_DIM;     i += blockDim.x) sb1[i] = b1[i];
    for (int i = tid; i < C_OUT;     i += blockDim.x) sb2[i] = b2[i];
    for (int i = tid; i < C_OUT * H_DIM; i += blockDim.x) {
        int o = i / H_DIM, k = i % H_DIM;
        sW2t[k * C_OUT + o] = W2[i];
    }
    __syncthreads();

    const int warp = tid >> 5;
    const int lane = tid & 31;
    const int warps_per_grid = (gridDim.x * blockDim.x) >> 5;

    for (int p = blockIdx.x * (blockDim.x >> 5) + warp; p < NPTS_TOTAL;
         p += warps_per_grid) {
        const float x0 = x[p * 3 + 0];
        const float x1 = x[p * 3 + 1];
        const float x2 = x[p * 3 + 2];
        if (lane == 0) {
            // match reference: sq = sum(x*x) left-to-right
            float s = x0 * x0;
            s = s + x1 * x1;
            s = s + x2 * x2;
            g_xpad[p] = make_float4(x0, x1, x2, s);
        }
        // h1 rows lane, lane+32
        #pragma unroll
        for (int r = lane; r < H_DIM; r += 32) {
            float v = fmaf(sW1[r * 3 + 2], x2,
                      fmaf(sW1[r * 3 + 1], x1, sW1[r * 3 + 0] * x0)) + sb1[r];
            sh1[warp][r] = fmaxf(v, 0.0f);
        }
        __syncwarp();
        // f channels lane + 32*j
        float acc0 = sb2[lane +  0];
        float acc1 = sb2[lane + 32];
        float acc2 = sb2[lane + 64];
        float acc3 = sb2[lane + 96];
        #pragma unroll
        for (int k = 0; k < H_DIM; k++) {
            const float h = sh1[warp][k];
            const float* wrow = &sW2t[k * C_OUT + lane];
            acc0 = fmaf(wrow[ 0], h, acc0);
            acc1 = fmaf(wrow[32], h, acc1);
            acc2 = fmaf(wrow[64], h, acc2);
            acc3 = fmaf(wrow[96], h, acc3);
        }
        float* fp = &g_f[(size_t)p * C_OUT];
        fp[lane +  0] = fmaxf(acc0, 0.0f);
        fp[lane + 32] = fmaxf(acc1, 0.0f);
        fp[lane + 64] = fmaxf(acc2, 0.0f);
        fp[lane + 96] = fmaxf(acc3, 0.0f);
        __syncwarp();
    }
}

// ---------------------------------------------------------------------------
// Kernel 2: one warp per query point n.
// Scan p in ascending order, 32 at a time. Keep first NSAMPLE qualifying
// (dist <= R2, reference formula (sq_n + sq_p) - 2*dot). For each kept
// neighbor, each lane fmax's a float4 of its feature row (coalesced 512B).
// Padding-with-first is a no-op under max (duplicates).
// ---------------------------------------------------------------------------
__global__ void group_max_kernel(float* __restrict__ out)
{
    const int gwarp = (blockIdx.x * blockDim.x + threadIdx.x) >> 5;
    const int lane  = threadIdx.x & 31;
    if (gwarp >= NPTS_TOTAL) return;

    const int b = gwarp >> 11;          // / N_PTS
    const int n = gwarp & (N_PTS - 1);

    const float4* __restrict__ xb = g_xpad + b * N_PTS;
    const float*  __restrict__ fb = g_f + (size_t)b * N_PTS * C_OUT;

    const float4 q = xb[n];

    float4 acc = make_float4(0.0f, 0.0f, 0.0f, 0.0f);  // relu outputs >= 0, self always qualifies
    int found = 0;

    for (int pb = 0; pb < N_PTS && found < NSAMPLE; pb += 32) {
        const int p = pb + lane;
        const float4 r = xb[p];
        const float dot = fmaf(q.z, r.z, fmaf(q.y, r.y, q.x * r.x));
        const float dist = (q.w + r.w) - 2.0f * dot;
        const bool qual = !(dist > R2);
        const unsigned m = __ballot_sync(0xffffffffu, qual);
        const int need = NSAMPLE - found;
        const int rank = __popc(m & ((1u << lane) - 1u));
        const bool take = qual && (rank < need);
        unsigned sel = __ballot_sync(0xffffffffu, take);
        found += __popc(sel);

        while (sel) {
            const int src = __ffs(sel) - 1;
            sel &= sel - 1u;
            const int pv = pb + src;
            const float4 fv =
                *reinterpret_cast<const float4*>(fb + (size_t)pv * C_OUT + lane * 4);
            acc.x = fmaxf(acc.x, fv.x);
            acc.y = fmaxf(acc.y, fv.y);
            acc.z = fmaxf(acc.z, fv.z);
            acc.w = fmaxf(acc.w, fv.w);
        }
    }

    // out shape (B, 128, N): out[(b*128 + c)*N + n], lane owns c = 4*lane .. 4*lane+3
    float* ob = out + ((size_t)b * C_OUT + lane * 4) * N_PTS + n;
    ob[0 * N_PTS] = acc.x;
    ob[1 * N_PTS] = acc.y;
    ob[2 * N_PTS] = acc.z;
    ob[3 * N_PTS] = acc.w;
}

extern "C" void kernel_launch(void* const* d_in, const int* in_sizes, int n_in,
                              void* d_out, int out_size)
{
    const float* x  = (const float*)d_in[0];
    const float* W1 = (const float*)d_in[1];
    const float* b1 = (const float*)d_in[2];
    const float* W2 = (const float*)d_in[3];
    const float* b2 = (const float*)d_in[4];
    float* out = (float*)d_out;

    // Kernel 1: 256 blocks x 256 threads (8 warps -> 8 points per iter per block)
    feat_kernel<<<256, 256>>>(x, W1, b1, W2, b2);

    // Kernel 2: one warp per point; 16384 warps / 8 warps-per-block
    group_max_kernel<<<NPTS_TOTAL / 8, 256>>>(out);
}

// round 3
// speedup vs baseline: 1.1907x; 1.1907x over previous
#include <cuda_runtime.h>
#include <cuda_bf16.h>

#define B_DIM 8
#define N_PTS 2048
#define NPTS_TOTAL (B_DIM * N_PTS)
#define C_OUT 128
#define H_DIM 64
#define NSAMPLE 64
#define R2 0.36f

// Scratch (allocation-free rule: __device__ globals)
__device__ float  g_f[NPTS_TOTAL * C_OUT];   // per-point 128-dim features (8 MB)
__device__ float4 g_xpad[NPTS_TOTAL];        // (x, y, z, x^2+y^2+z^2)

// ---------------------------------------------------------------------------
// Kernel 1: per-point MLP features.  One warp per point (strided).
// sW2t padded to stride 129 -> conflict-free staging AND reading.
// ---------------------------------------------------------------------------
#define W2T_STRIDE 129

__global__ void feat_kernel(const float* __restrict__ x,
                            const float* __restrict__ W1,
                            const float* __restrict__ b1,
                            const float* __restrict__ W2,
                            const float* __restrict__ b2)
{
    __shared__ float sW1[H_DIM * 3];
    __shared__ float sb1[H_DIM];
    __shared__ float sW2t[H_DIM * W2T_STRIDE];   // [k][o], padded
    __shared__ float sb2[C_OUT];
    __shared__ float sh1[8][H_DIM + 1];          // per-warp h1 (pad row)

    const int tid = threadIdx.x;
    for (int i = tid; i < H_DIM * 3; i += blockDim.x) sW1[i] = W1[i];
    for (int i = tid; i < H_DIM;     i += blockDim.x) sb1[i] = b1[i];
    for (int i = tid; i < C_OUT;     i += blockDim.x) sb2[i] = b2[i];
    // W2 row-major [o][k]; coalesced read, conflict-free transpose write
    for (int i = tid; i < C_OUT * H_DIM; i += blockDim.x) {
        const int o = i >> 6, k = i & 63;
        sW2t[k * W2T_STRIDE + o] = W2[i];
    }
    __syncthreads();

    const int warp = tid >> 5;
    const int lane = tid & 31;
    const int warps_per_grid = (gridDim.x * blockDim.x) >> 5;

    for (int p = blockIdx.x * (blockDim.x >> 5) + warp; p < NPTS_TOTAL;
         p += warps_per_grid) {
        const float x0 = x[p * 3 + 0];
        const float x1 = x[p * 3 + 1];
        const float x2 = x[p * 3 + 2];
        if (lane == 0) {
            // match reference: sq = sum(x*x) left-to-right
            float s = x0 * x0;
            s = s + x1 * x1;
            s = s + x2 * x2;
            g_xpad[p] = make_float4(x0, x1, x2, s);
        }
        #pragma unroll
        for (int r = lane; r < H_DIM; r += 32) {
            float v = fmaf(sW1[r * 3 + 2], x2,
                      fmaf(sW1[r * 3 + 1], x1, sW1[r * 3 + 0] * x0)) + sb1[r];
            sh1[warp][r] = fmaxf(v, 0.0f);
        }
        __syncwarp();
        float acc0 = sb2[lane +  0];
        float acc1 = sb2[lane + 32];
        float acc2 = sb2[lane + 64];
        float acc3 = sb2[lane + 96];
        #pragma unroll 8
        for (int k = 0; k < H_DIM; k++) {
            const float h = sh1[warp][k];
            const float* wrow = &sW2t[k * W2T_STRIDE + lane];
            acc0 = fmaf(wrow[ 0], h, acc0);
            acc1 = fmaf(wrow[32], h, acc1);
            acc2 = fmaf(wrow[64], h, acc2);
            acc3 = fmaf(wrow[96], h, acc3);
        }
        float* fp = &g_f[(size_t)p * C_OUT];
        fp[lane +  0] = fmaxf(acc0, 0.0f);
        fp[lane + 32] = fmaxf(acc1, 0.0f);
        fp[lane + 64] = fmaxf(acc2, 0.0f);
        fp[lane + 96] = fmaxf(acc3, 0.0f);
        __syncwarp();
    }
}

// ---------------------------------------------------------------------------
// Kernel 2: 1024-thread block = 32 warps = 32 consecutive queries of batch b.
// Phase 1: ballot-scan first NSAMPLE qualifying indices into smem.
// Phase 2: gather with 4 independent accumulators (MLP=4).
// Phase 3: transpose via smem -> fully coalesced 128B output stores.
// ---------------------------------------------------------------------------
__global__ __launch_bounds__(1024, 1)
void group_max_kernel(float* __restrict__ out)
{
    __shared__ int   sidx[32][NSAMPLE];      // accepted indices per query
    __shared__ float sout[C_OUT][33];        // [channel][query], padded

    const int tid  = threadIdx.x;
    const int q    = tid >> 5;               // warp = local query 0..31
    const int lane = tid & 31;

    // 64 blocks per batch (2048/32)
    const int b  = blockIdx.x >> 6;
    const int n0 = (blockIdx.x & 63) << 5;
    const int n  = n0 + q;

    const float4* __restrict__ xb = g_xpad + b * N_PTS;
    const float*  __restrict__ fb = g_f + (size_t)b * N_PTS * C_OUT;

    const float4 qc = xb[n];

    // ---- Phase 1: find first NSAMPLE qualifying indices ----
    int found = 0;
    for (int pb = 0; pb < N_PTS && found < NSAMPLE; pb += 32) {
        const float4 r = xb[pb + lane];
        const float dot  = fmaf(qc.z, r.z, fmaf(qc.y, r.y, qc.x * r.x));
        const float dist = (qc.w + r.w) - 2.0f * dot;
        const bool  qual = !(dist > R2);
        const unsigned m = __ballot_sync(0xffffffffu, qual);
        const int need = NSAMPLE - found;
        const int rank = __popc(m & ((1u << lane) - 1u));
        const bool take = qual && (rank < need);
        if (take) sidx[q][found + rank] = pb + lane;
        found += __popc(__ballot_sync(0xffffffffu, take));
    }
    __syncwarp();
    const int last = found - 1;              // found >= 1 (self always qualifies)

    // ---- Phase 2: gather-max with 4-wide ILP ----
    float4 a0 = make_float4(0.f, 0.f, 0.f, 0.f);
    float4 a1 = a0, a2 = a0, a3 = a0;        // relu outputs >= 0
    const int coff = lane * 4;
    for (int j = 0; j < found; j += 4) {
        const int i0 = sidx[q][j];
        const int i1 = sidx[q][min(j + 1, last)];
        const int i2 = sidx[q][min(j + 2, last)];
        const int i3 = sidx[q][min(j + 3, last)];
        const float4 v0 = *reinterpret_cast<const float4*>(fb + (size_t)i0 * C_OUT + coff);
        const float4 v1 = *reinterpret_cast<const float4*>(fb + (size_t)i1 * C_OUT + coff);
        const float4 v2 = *reinterpret_cast<const float4*>(fb + (size_t)i2 * C_OUT + coff);
        const float4 v3 = *reinterpret_cast<const float4*>(fb + (size_t)i3 * C_OUT + coff);
        a0.x = fmaxf(a0.x, v0.x); a0.y = fmaxf(a0.y, v0.y);
        a0.z = fmaxf(a0.z, v0.z); a0.w = fmaxf(a0.w, v0.w);
        a1.x = fmaxf(a1.x, v1.x); a1.y = fmaxf(a1.y, v1.y);
        a1.z = fmaxf(a1.z, v1.z); a1.w = fmaxf(a1.w, v1.w);
        a2.x = fmaxf(a2.x, v2.x); a2.y = fmaxf(a2.y, v2.y);
        a2.z = fmaxf(a2.z, v2.z); a2.w = fmaxf(a2.w, v2.w);
        a3.x = fmaxf(a3.x, v3.x); a3.y = fmaxf(a3.y, v3.y);
        a3.z = fmaxf(a3.z, v3.z); a3.w = fmaxf(a3.w, v3.w);
    }
    a0.x = fmaxf(fmaxf(a0.x, a1.x), fmaxf(a2.x, a3.x));
    a0.y = fmaxf(fmaxf(a0.y, a1.y), fmaxf(a2.y, a3.y));
    a0.z = fmaxf(fmaxf(a0.z, a1.z), fmaxf(a2.z, a3.z));
    a0.w = fmaxf(fmaxf(a0.w, a1.w), fmaxf(a2.w, a3.w));

    // ---- Phase 3: smem transpose, coalesced store ----
    sout[coff + 0][q] = a0.x;
    sout[coff + 1][q] = a0.y;
    sout[coff + 2][q] = a0.z;
    sout[coff + 3][q] = a0.w;
    __syncthreads();

    // out shape (B, 128, N). Thread -> (c, nq): consecutive lanes = consecutive n.
    const int nq = tid & 31;
    const int c0 = tid >> 5;
    float* ob = out + ((size_t)b * C_OUT) * N_PTS + n0 + nq;
    #pragma unroll
    for (int i = 0; i < 4; i++) {
        const int c = c0 + 32 * i;
        ob[(size_t)c * N_PTS] = sout[c][nq];
    }
}

extern "C" void kernel_launch(void* const* d_in, const int* in_sizes, int n_in,
                              void* d_out, int out_size)
{
    const float* x  = (const float*)d_in[0];
    const float* W1 = (const float*)d_in[1];
    const float* b1 = (const float*)d_in[2];
    const float* W2 = (const float*)d_in[3];
    const float* b2 = (const float*)d_in[4];
    float* out = (float*)d_out;

    feat_kernel<<<512, 256>>>(x, W1, b1, W2, b2);
    group_max_kernel<<<NPTS_TOTAL / 32, 1024>>>(out);
}